// round 1
// baseline (speedup 1.0000x reference)
#include <cuda_runtime.h>
#include <cuda_bf16.h>
#include <math_constants.h>

// Problem constants
#define BQ 1024
#define DD 512
#define NN 131072
#define KK 16

// ---------------------------------------------------------------------------
// Scratch (__device__ globals; no allocation allowed)
// ---------------------------------------------------------------------------
__device__ float g_qn[BQ * DD];                       // normalized queries, 2 MB
__device__ float g_sims[(size_t)BQ * NN];             // similarity matrix, 512 MB
__device__ int   g_topk_idx[BQ * KK];                 // selected indices

// ---------------------------------------------------------------------------
// Kernel 1: normalize queries (one block per query row)
// ---------------------------------------------------------------------------
__global__ __launch_bounds__(128) void normalize_kernel(const float* __restrict__ q) {
    int row = blockIdx.x;
    const float* src = q + (size_t)row * DD;
    float v[4];
    float s = 0.f;
#pragma unroll
    for (int i = 0; i < 4; i++) {
        v[i] = src[threadIdx.x + i * 128];
        s += v[i] * v[i];
    }
#pragma unroll
    for (int o = 16; o > 0; o >>= 1) s += __shfl_xor_sync(0xffffffffu, s, o);
    __shared__ float red[4];
    if ((threadIdx.x & 31) == 0) red[threadIdx.x >> 5] = s;
    __syncthreads();
    float tot = red[0] + red[1] + red[2] + red[3];
    float inv = rsqrtf(tot);
#pragma unroll
    for (int i = 0; i < 4; i++)
        g_qn[(size_t)row * DD + threadIdx.x + i * 128] = v[i] * inv;
}

// ---------------------------------------------------------------------------
// Kernel 2: SGEMM  sims[B,N] = qn[B,D] * weight[D,N]
// Classic 128x128 CTA tile, 8x8 per thread, BK=8, 256 threads.
// ---------------------------------------------------------------------------
#define BM 128
#define BN 128
#define BKC 8
#define TM 8
#define TN 8

__global__ __launch_bounds__(256) void sgemm_kernel(const float* __restrict__ Bw) {
    const int cCol = blockIdx.x;   // n tile (0..1023)
    const int cRow = blockIdx.y;   // m tile (0..7)

    __shared__ float As[BKC][BM];
    __shared__ float Bs[BKC][BN];

    const int tid  = threadIdx.x;
    const int aRow = tid >> 1;            // 0..127
    const int aCol = (tid & 1) * 4;       // 0 or 4
    const int bRow = tid >> 5;            // 0..7
    const int bCol = (tid & 31) * 4;      // 0..124

    const float* Aptr = g_qn + (size_t)(cRow * BM) * DD;
    const float* Bptr = Bw + (size_t)cCol * BN;

    const int tRow = (tid >> 4) * TM;     // 0..120
    const int tCol = (tid & 15) * TN;     // 0..120

    float acc[TM][TN] = {};
    float regM[TM], regN[TN];

    for (int k0 = 0; k0 < DD; k0 += BKC) {
        float4 av = *(const float4*)(Aptr + (size_t)aRow * DD + k0 + aCol);
        As[aCol + 0][aRow] = av.x;
        As[aCol + 1][aRow] = av.y;
        As[aCol + 2][aRow] = av.z;
        As[aCol + 3][aRow] = av.w;
        float4 bv = *(const float4*)(Bptr + (size_t)(k0 + bRow) * NN + bCol);
        *(float4*)&Bs[bRow][bCol] = bv;
        __syncthreads();

#pragma unroll
        for (int k = 0; k < BKC; k++) {
#pragma unroll
            for (int i = 0; i < TM; i++) regM[i] = As[k][tRow + i];
#pragma unroll
            for (int j = 0; j < TN; j++) regN[j] = Bs[k][tCol + j];
#pragma unroll
            for (int i = 0; i < TM; i++)
#pragma unroll
                for (int j = 0; j < TN; j++)
                    acc[i][j] += regM[i] * regN[j];
        }
        __syncthreads();
    }

    float* Cptr = g_sims + (size_t)(cRow * BM + tRow) * NN + (size_t)cCol * BN + tCol;
#pragma unroll
    for (int i = 0; i < TM; i++) {
        float4 v0 = make_float4(acc[i][0], acc[i][1], acc[i][2], acc[i][3]);
        float4 v1 = make_float4(acc[i][4], acc[i][5], acc[i][6], acc[i][7]);
        *(float4*)(Cptr + (size_t)i * NN)     = v0;
        *(float4*)(Cptr + (size_t)i * NN + 4) = v1;
    }
}

// ---------------------------------------------------------------------------
// Kernel 3: per-query top-16 over the sims row (one block per query)
// Stable tie-break: smaller index wins on equal score (matches jax.lax.top_k).
// ---------------------------------------------------------------------------
__global__ __launch_bounds__(256) void topk_kernel(const float* __restrict__ label,
                                                   float* __restrict__ out_scores,
                                                   float* __restrict__ out_idx_f,
                                                   float* __restrict__ out_labels) {
    const int qrow = blockIdx.x;
    const float* row = g_sims + (size_t)qrow * NN;

    // thread-local running top-16 (ascending: tv[0] is the min)
    float tv[KK];
    int   ti[KK];
#pragma unroll
    for (int i = 0; i < KK; i++) { tv[i] = -CUDART_INF_F; ti[i] = 0x7fffffff; }

    for (int n = threadIdx.x; n < NN; n += 256) {
        float x = row[n];
        if (x > tv[0]) {
            int pos = 0;
#pragma unroll
            for (int s = 0; s < KK - 1; s++) {
                if (pos == s && tv[s + 1] < x) {
                    tv[s] = tv[s + 1]; ti[s] = ti[s + 1]; pos = s + 1;
                }
            }
            tv[pos] = x; ti[pos] = n;
        }
    }

    __shared__ float sv[256 * KK];
    __shared__ int   si[256 * KK];
#pragma unroll
    for (int i = 0; i < KK; i++) {
        sv[threadIdx.x * KK + i] = tv[i];
        si[threadIdx.x * KK + i] = ti[i];
    }
    __syncthreads();

    __shared__ float redv[256];
    __shared__ int   redp[256];

    for (int sel = 0; sel < KK; sel++) {
        float best = -CUDART_INF_F;
        int   bpos = -1;
        int   bidx = 0x7fffffff;
        for (int j = threadIdx.x; j < 256 * KK; j += 256) {
            float v = sv[j];
            int  id = si[j];
            if (v > best || (v == best && id < bidx)) { best = v; bpos = j; bidx = id; }
        }
        redv[threadIdx.x] = best;
        redp[threadIdx.x] = bpos;
        __syncthreads();
        for (int off = 128; off > 0; off >>= 1) {
            if (threadIdx.x < off) {
                float v1 = redv[threadIdx.x],       v2 = redv[threadIdx.x + off];
                int   p1 = redp[threadIdx.x],       p2 = redp[threadIdx.x + off];
                int   i1 = (p1 >= 0) ? si[p1] : 0x7fffffff;
                int   i2 = (p2 >= 0) ? si[p2] : 0x7fffffff;
                if (v2 > v1 || (v2 == v1 && i2 < i1)) {
                    redv[threadIdx.x] = v2; redp[threadIdx.x] = p2;
                }
            }
            __syncthreads();
        }
        if (threadIdx.x == 0) {
            int p = redp[0];
            int nidx = si[p];
            float val = redv[0];
            out_scores[qrow * KK + sel] = val;
            out_idx_f [qrow * KK + sel] = (float)nidx;
            out_labels[qrow * KK + sel] = label[nidx];
            g_topk_idx[qrow * KK + sel] = nidx;
            sv[p] = -CUDART_INF_F;   // remove winner
        }
        __syncthreads();
    }
}

// ---------------------------------------------------------------------------
// Kernel 4: gather top_k_seqs = weight.T[idx]  (column gather from weight[D,N])
// ---------------------------------------------------------------------------
__global__ __launch_bounds__(128) void gather_kernel(const float* __restrict__ weight,
                                                     float* __restrict__ out_seqs) {
    const int b = blockIdx.x;             // 0..B*K-1
    const int n = g_topk_idx[b];
    float* dst = out_seqs + (size_t)b * DD;
#pragma unroll 4
    for (int d = threadIdx.x; d < DD; d += 128)
        dst[d] = weight[(size_t)d * NN + n];
}

// ---------------------------------------------------------------------------
// Launcher
// ---------------------------------------------------------------------------
extern "C" void kernel_launch(void* const* d_in, const int* in_sizes, int n_in,
                              void* d_out, int out_size) {
    const float* queries = (const float*)d_in[0];   // [1024, 512]
    const float* weight  = (const float*)d_in[1];   // [512, 131072]
    const float* label   = (const float*)d_in[2];   // [131072]

    float* out = (float*)d_out;
    // output layout: scores[B*K] | indices[B*K] (as f32) | seqs[B*K*D] | labels[B*K]
    float* out_scores = out;
    float* out_idx_f  = out + BQ * KK;
    float* out_seqs   = out + 2 * BQ * KK;
    float* out_labels = out + 2 * BQ * KK + (size_t)BQ * KK * DD;

    normalize_kernel<<<BQ, 128>>>(queries);
    dim3 grid(NN / BN, BQ / BM);
    sgemm_kernel<<<grid, 256>>>(weight);
    topk_kernel<<<BQ, 256>>>(label, out_scores, out_idx_f, out_labels);
    gather_kernel<<<BQ * KK, 128>>>(weight, out_seqs);
}

// round 4
// speedup vs baseline: 5.4626x; 5.4626x over previous
#include <cuda_runtime.h>
#include <cuda_bf16.h>
#include <math_constants.h>
#include <cstdint>

// Problem constants
#define BQ 1024
#define DD 512
#define NN 131072
#define KK 16
#define NCAND 32

// ---------------------------------------------------------------------------
// Helpers
// ---------------------------------------------------------------------------
__device__ __forceinline__ uint32_t smem_u32(const void* p) {
    uint32_t a;
    asm("{ .reg .u64 t; cvta.to.shared.u64 t, %1; cvt.u32.u64 %0, t; }" : "=r"(a) : "l"(p));
    return a;
}
__device__ __forceinline__ uint32_t sw128(uint32_t o) { return o ^ ((o >> 3) & 0x70); }

#define CP_ASYNC16(smem_addr, gptr) \
    asm volatile("cp.async.cg.shared.global [%0], [%1], 16;" :: "r"(smem_addr), "l"(gptr))
#define CP_COMMIT() asm volatile("cp.async.commit_group;")
#define CP_WAIT(N)  asm volatile("cp.async.wait_group %0;" :: "n"(N))

#define LDMATRIX_X4(r0, r1, r2, r3, addr) \
    asm volatile("ldmatrix.sync.aligned.m8n8.x4.shared.b16 {%0,%1,%2,%3}, [%4];" \
        : "=r"(r0), "=r"(r1), "=r"(r2), "=r"(r3) : "r"(addr))

#define MMA_BF16(c, a, b) \
    asm volatile("mma.sync.aligned.m16n8k16.row.col.f32.bf16.bf16.f32 " \
        "{%0,%1,%2,%3}, {%4,%5,%6,%7}, {%8,%9}, {%0,%1,%2,%3};" \
        : "+f"((c)[0]), "+f"((c)[1]), "+f"((c)[2]), "+f"((c)[3]) \
        : "r"((a)[0]), "r"((a)[1]), "r"((a)[2]), "r"((a)[3]), "r"((b)[0]), "r"((b)[1]))

// ---------------------------------------------------------------------------
// Scratch (__device__ globals; no allocation allowed)
// ---------------------------------------------------------------------------
__device__ float          g_qn[BQ * DD];                    // normalized queries fp32
__device__ __nv_bfloat16  g_qnb[BQ * DD];                   // normalized queries bf16
__device__ float          g_wt[(size_t)NN * DD];            // W^T fp32 [N, D] 256MB
__device__ __nv_bfloat16  g_wtb[(size_t)NN * DD];           // W^T bf16 [N, D] 128MB
__device__ __nv_bfloat16  g_simsb[(size_t)BQ * NN];         // sims bf16   256MB
__device__ int            g_cand[BQ * NCAND];               // candidate indices

// ---------------------------------------------------------------------------
// Kernel 1: normalize queries -> fp32 + bf16
// ---------------------------------------------------------------------------
__global__ __launch_bounds__(128) void normalize_kernel(const float* __restrict__ q) {
    int row = blockIdx.x;
    const float* src = q + (size_t)row * DD;
    float v[4];
    float s = 0.f;
#pragma unroll
    for (int i = 0; i < 4; i++) { v[i] = src[threadIdx.x + i * 128]; s += v[i] * v[i]; }
#pragma unroll
    for (int o = 16; o > 0; o >>= 1) s += __shfl_xor_sync(0xffffffffu, s, o);
    __shared__ float red[4];
    if ((threadIdx.x & 31) == 0) red[threadIdx.x >> 5] = s;
    __syncthreads();
    float inv = rsqrtf(red[0] + red[1] + red[2] + red[3]);
#pragma unroll
    for (int i = 0; i < 4; i++) {
        float f = v[i] * inv;
        int d = threadIdx.x + i * 128;
        g_qn[(size_t)row * DD + d]  = f;
        g_qnb[(size_t)row * DD + d] = __float2bfloat16(f);
    }
}

// ---------------------------------------------------------------------------
// Kernel 2: transpose W[D,N] -> W_t[N,D] (fp32 + bf16)
// ---------------------------------------------------------------------------
__global__ __launch_bounds__(256) void transpose_kernel(const float* __restrict__ W) {
    __shared__ float tile[32][33];
    int bx = blockIdx.x, by = blockIdx.y;
    int tx = threadIdx.x, ty = threadIdx.y;   // 32 x 8
#pragma unroll
    for (int k = 0; k < 4; k++) {
        int d = by * 32 + ty + k * 8;
        int n = bx * 32 + tx;
        tile[ty + k * 8][tx] = W[(size_t)d * NN + n];
    }
    __syncthreads();
#pragma unroll
    for (int k = 0; k < 4; k++) {
        int n = bx * 32 + ty + k * 8;
        int d = by * 32 + tx;
        float v = tile[tx][ty + k * 8];
        g_wt [(size_t)n * DD + d] = v;
        g_wtb[(size_t)n * DD + d] = __float2bfloat16(v);
    }
}

// ---------------------------------------------------------------------------
// Kernel 3: bf16 HMMA GEMM  sims[B,N] = Qn x W_t^T  (writes bf16 sims)
// CTA tile 128x128, BK=64, 8 warps (2m x 4n), warp tile 64x32.
// cp.async double-buffered, SW128-swizzled SMEM, ldmatrix fragments.
// ---------------------------------------------------------------------------
#define BKG 64
#define SMEM_TOTAL 65536   // A0 16K | A1 16K | B0 16K | B1 16K ; C-stage reuses 32K

__global__ __launch_bounds__(256, 2) void gemm_kernel() {
    extern __shared__ char smem[];
    const uint32_t sb = smem_u32(smem);
    const int tid = threadIdx.x, wid = tid >> 5, lane = tid & 31;
    const int q0 = blockIdx.x * 128;
    const int nb = blockIdx.y * 128;

    const uint32_t AOFF[2] = {0u, 16384u};
    const uint32_t BOFF[2] = {32768u, 49152u};

    const int ldrow = tid >> 3;          // 0..31 base row (x4 iters -> 128 rows)
    const int ldseg = tid & 7;           // 16B segment within 128B row

    auto issue = [&](int kc, int buf) {
        const __nv_bfloat16* As = g_qnb + (size_t)q0 * DD + kc * BKG;
        const __nv_bfloat16* Bs = g_wtb + (size_t)nb * DD + kc * BKG;
#pragma unroll
        for (int i = 0; i < 4; i++) {
            int row = ldrow + i * 32;
            uint32_t off = sw128((uint32_t)(row * 128 + ldseg * 16));
            CP_ASYNC16(sb + AOFF[buf] + off, As + (size_t)row * DD + ldseg * 8);
            CP_ASYNC16(sb + BOFF[buf] + off, Bs + (size_t)row * DD + ldseg * 8);
        }
        CP_COMMIT();
    };

    float c[4][4][4];
#pragma unroll
    for (int mi = 0; mi < 4; mi++)
#pragma unroll
        for (int ni = 0; ni < 4; ni++)
#pragma unroll
            for (int r = 0; r < 4; r++) c[mi][ni][r] = 0.f;

    const int wm = (wid >> 2) * 64;      // warp m origin
    const int wn = (wid & 3) * 32;       // warp n origin
    const int lrow = lane & 15;          // ldmatrix row within 16-row group
    const int lkh  = lane >> 4;          // ldmatrix k-half selector

    issue(0, 0);

#pragma unroll 1
    for (int kc = 0; kc < 8; kc++) {
        const int buf = kc & 1;
        if (kc < 7) { issue(kc + 1, buf ^ 1); CP_WAIT(1); }
        else        { CP_WAIT(0); }
        __syncthreads();

        const uint32_t ab = sb + AOFF[buf];
        const uint32_t bb = sb + BOFF[buf];
#pragma unroll
        for (int ks = 0; ks < 4; ks++) {
            const int k0 = ks * 16;
            uint32_t a[4][4];
#pragma unroll
            for (int mi = 0; mi < 4; mi++) {
                uint32_t addr = ab + sw128((uint32_t)((wm + mi * 16 + lrow) * 128 + (k0 + lkh * 8) * 2));
                LDMATRIX_X4(a[mi][0], a[mi][1], a[mi][2], a[mi][3], addr);
            }
            uint32_t b[4][2];
#pragma unroll
            for (int nj = 0; nj < 2; nj++) {
                uint32_t r0, r1, r2, r3;
                uint32_t addr = bb + sw128((uint32_t)((wn + nj * 16 + lrow) * 128 + (k0 + lkh * 8) * 2));
                LDMATRIX_X4(r0, r1, r2, r3, addr);
                b[2 * nj][0] = r0; b[2 * nj + 1][0] = r1;
                b[2 * nj][1] = r2; b[2 * nj + 1][1] = r3;
            }
#pragma unroll
            for (int mi = 0; mi < 4; mi++)
#pragma unroll
                for (int ni = 0; ni < 4; ni++)
                    MMA_BF16(c[mi][ni], a[mi], b[ni]);
        }
        __syncthreads();
    }

    // ---- epilogue: stage C tile (128x128 bf16, 32KB) in smem, coalesced store ----
    const int crow = lane >> 2;
    const int ccol2 = (lane & 3) * 2;
#pragma unroll
    for (int mi = 0; mi < 4; mi++)
#pragma unroll
        for (int ni = 0; ni < 4; ni++) {
            int m = wm + mi * 16 + crow;
            int n = wn + ni * 8 + ccol2;
            __nv_bfloat162 p0 = __float22bfloat162_rn(make_float2(c[mi][ni][0], c[mi][ni][1]));
            __nv_bfloat162 p1 = __float22bfloat162_rn(make_float2(c[mi][ni][2], c[mi][ni][3]));
            *(__nv_bfloat162*)(smem + m * 256 + n * 2)       = p0;
            *(__nv_bfloat162*)(smem + (m + 8) * 256 + n * 2) = p1;
        }
    __syncthreads();
#pragma unroll
    for (int i = 0; i < 8; i++) {
        int idx = tid + i * 256;        // 0..2047
        int m = idx >> 4, ch = idx & 15;
        uint4 v = *(uint4*)(smem + m * 256 + ch * 16);
        *(uint4*)(g_simsb + (size_t)(q0 + m) * NN + nb + ch * 8) = v;
    }
}

// ---------------------------------------------------------------------------
// Kernel 4: per-query top-32 candidates from bf16 sims
// ---------------------------------------------------------------------------
#define TL 8   // per-thread local top-8
__global__ __launch_bounds__(256) void cand_kernel() {
    const int q = blockIdx.x;
    const uint4* row = (const uint4*)(g_simsb + (size_t)q * NN);

    float tv[TL]; int ti[TL];
#pragma unroll
    for (int i = 0; i < TL; i++) { tv[i] = -CUDART_INF_F; ti[i] = 0x7fffffff; }

    for (int i = 0; i < 64; i++) {
        int j = threadIdx.x + i * 256;
        uint4 v = row[j];
        uint32_t w[4] = {v.x, v.y, v.z, v.w};
#pragma unroll
        for (int e = 0; e < 4; e++) {
            __nv_bfloat162 b2 = *(__nv_bfloat162*)&w[e];
            float f0 = __low2float(b2), f1 = __high2float(b2);
            int n0 = j * 8 + e * 2;
#pragma unroll
            for (int h = 0; h < 2; h++) {
                float x = h ? f1 : f0;
                int   n = n0 + h;
                if (x > tv[0]) {
                    int pos = 0;
#pragma unroll
                    for (int s = 0; s < TL - 1; s++)
                        if (pos == s && tv[s + 1] < x) {
                            tv[s] = tv[s + 1]; ti[s] = ti[s + 1]; pos = s + 1;
                        }
                    tv[pos] = x; ti[pos] = n;
                }
            }
        }
    }

    __shared__ float sv[256 * TL];
    __shared__ int   si[256 * TL];
#pragma unroll
    for (int i = 0; i < TL; i++) {
        sv[threadIdx.x * TL + i] = tv[i];
        si[threadIdx.x * TL + i] = ti[i];
    }
    __syncthreads();

    __shared__ float redv[256];
    __shared__ int   redp[256];

    for (int sel = 0; sel < NCAND; sel++) {
        float best = -CUDART_INF_F; int bpos = -1; int bidx = 0x7fffffff;
        for (int j = threadIdx.x; j < 256 * TL; j += 256) {
            float v = sv[j]; int id = si[j];
            if (v > best || (v == best && id < bidx)) { best = v; bpos = j; bidx = id; }
        }
        redv[threadIdx.x] = best; redp[threadIdx.x] = bpos;
        __syncthreads();
        for (int off = 128; off > 0; off >>= 1) {
            if (threadIdx.x < off) {
                float v1 = redv[threadIdx.x], v2 = redv[threadIdx.x + off];
                int   p1 = redp[threadIdx.x], p2 = redp[threadIdx.x + off];
                int   i1 = (p1 >= 0) ? si[p1] : 0x7fffffff;
                int   i2 = (p2 >= 0) ? si[p2] : 0x7fffffff;
                if (v2 > v1 || (v2 == v1 && i2 < i1)) { redv[threadIdx.x] = v2; redp[threadIdx.x] = p2; }
            }
            __syncthreads();
        }
        if (threadIdx.x == 0) {
            int p = redp[0];
            g_cand[q * NCAND + sel] = si[p];
            sv[p] = -CUDART_INF_F;
        }
        __syncthreads();
    }
}

// ---------------------------------------------------------------------------
// Kernel 5: rescore 32 candidates with SEQUENTIAL fp32 FMA over d (matches the
// reference matmul's accumulation-order rounding — the round-1 passing regime),
// select top-16, write all outputs.
// ---------------------------------------------------------------------------
#define CHUNK 128
#define CPITCH 129   // conflict-free smem pitch

__global__ __launch_bounds__(256) void refine_kernel(const float* __restrict__ label,
                                                     float* __restrict__ out_scores,
                                                     float* __restrict__ out_idx_f,
                                                     float* __restrict__ out_seqs,
                                                     float* __restrict__ out_labels) {
    const int q = blockIdx.x;
    const int tid = threadIdx.x;

    __shared__ float qn_s[DD];
    __shared__ float chunk[NCAND * CPITCH];
    __shared__ float cv[NCAND];
    __shared__ int   ci[NCAND];
    __shared__ int   sel_idx[KK];

    if (tid < NCAND) ci[tid] = g_cand[q * NCAND + tid];
    for (int d = tid; d < DD; d += 256) qn_s[d] = g_qn[(size_t)q * DD + d];
    __syncthreads();

    float acc = 0.f;   // live only for tid < NCAND
#pragma unroll 1
    for (int ch = 0; ch < DD / CHUNK; ch++) {
        // coalesced stage: 32 candidate rows x 128 d-values
        for (int idx = tid; idx < NCAND * CHUNK; idx += 256) {
            int c = idx >> 7, d = idx & (CHUNK - 1);
            chunk[c * CPITCH + d] = g_wt[(size_t)ci[c] * DD + ch * CHUNK + d];
        }
        __syncthreads();
        if (tid < NCAND) {
            // strictly sequential FMA chain in increasing d
#pragma unroll
            for (int d = 0; d < CHUNK; d++)
                acc = fmaf(chunk[tid * CPITCH + d], qn_s[ch * CHUNK + d], acc);
        }
        __syncthreads();
    }
    if (tid < NCAND) cv[tid] = acc;
    __syncthreads();

    if (tid == 0) {
        bool used[NCAND] = {};
        for (int r = 0; r < KK; r++) {
            float best = -CUDART_INF_F; int bj = -1; int bidx = 0x7fffffff;
            for (int j = 0; j < NCAND; j++) {
                if (used[j]) continue;
                if (cv[j] > best || (cv[j] == best && ci[j] < bidx)) {
                    best = cv[j]; bj = j; bidx = ci[j];
                }
            }
            used[bj] = true;
            sel_idx[r] = ci[bj];
            out_scores[q * KK + r] = best;
            out_idx_f [q * KK + r] = (float)ci[bj];
            out_labels[q * KK + r] = label[ci[bj]];
        }
    }
    __syncthreads();

#pragma unroll 1
    for (int r = 0; r < KK; r++) {
        const float* row = g_wt + (size_t)sel_idx[r] * DD;
        float* dst = out_seqs + ((size_t)q * KK + r) * DD;
        for (int d = tid; d < DD; d += 256) dst[d] = row[d];
    }
}

// ---------------------------------------------------------------------------
// Launcher
// ---------------------------------------------------------------------------
extern "C" void kernel_launch(void* const* d_in, const int* in_sizes, int n_in,
                              void* d_out, int out_size) {
    const float* queries = (const float*)d_in[0];   // [1024, 512]
    const float* weight  = (const float*)d_in[1];   // [512, 131072]
    const float* label   = (const float*)d_in[2];   // [131072]

    float* out = (float*)d_out;
    float* out_scores = out;
    float* out_idx_f  = out + BQ * KK;
    float* out_seqs   = out + 2 * BQ * KK;
    float* out_labels = out + 2 * BQ * KK + (size_t)BQ * KK * DD;

    cudaFuncSetAttribute(gemm_kernel, cudaFuncAttributeMaxDynamicSharedMemorySize, SMEM_TOTAL);

    normalize_kernel<<<BQ, 128>>>(queries);
    transpose_kernel<<<dim3(NN / 32, DD / 32), dim3(32, 8)>>>(weight);
    gemm_kernel<<<dim3(BQ / 128, NN / 128), 256, SMEM_TOTAL>>>();
    cand_kernel<<<BQ, 256>>>();
    refine_kernel<<<BQ, 256>>>(label, out_scores, out_idx_f, out_seqs, out_labels);
}

// round 5
// speedup vs baseline: 6.0885x; 1.1146x over previous
#include <cuda_runtime.h>
#include <cuda_bf16.h>
#include <math_constants.h>
#include <cstdint>

// Problem constants
#define BQ 1024
#define DD 512
#define NN 131072
#define KK 16
#define NCAND 32

// ---------------------------------------------------------------------------
// Helpers
// ---------------------------------------------------------------------------
__device__ __forceinline__ uint32_t smem_u32(const void* p) {
    uint32_t a;
    asm("{ .reg .u64 t; cvta.to.shared.u64 t, %1; cvt.u32.u64 %0, t; }" : "=r"(a) : "l"(p));
    return a;
}
__device__ __forceinline__ uint32_t sw128(uint32_t o) { return o ^ ((o >> 3) & 0x70); }

#define CP_ASYNC16(smem_addr, gptr) \
    asm volatile("cp.async.cg.shared.global [%0], [%1], 16;" :: "r"(smem_addr), "l"(gptr))
#define CP_COMMIT() asm volatile("cp.async.commit_group;")
#define CP_WAIT(N)  asm volatile("cp.async.wait_group %0;" :: "n"(N))

#define LDMATRIX_X4(r0, r1, r2, r3, addr) \
    asm volatile("ldmatrix.sync.aligned.m8n8.x4.shared.b16 {%0,%1,%2,%3}, [%4];" \
        : "=r"(r0), "=r"(r1), "=r"(r2), "=r"(r3) : "r"(addr))

#define MMA_BF16(c, a, b) \
    asm volatile("mma.sync.aligned.m16n8k16.row.col.f32.bf16.bf16.f32 " \
        "{%0,%1,%2,%3}, {%4,%5,%6,%7}, {%8,%9}, {%0,%1,%2,%3};" \
        : "+f"((c)[0]), "+f"((c)[1]), "+f"((c)[2]), "+f"((c)[3]) \
        : "r"((a)[0]), "r"((a)[1]), "r"((a)[2]), "r"((a)[3]), "r"((b)[0]), "r"((b)[1]))

// ---------------------------------------------------------------------------
// Scratch (__device__ globals; no allocation allowed)
// ---------------------------------------------------------------------------
__device__ float          g_qn[BQ * DD];
__device__ __nv_bfloat16  g_qnb[BQ * DD];
__device__ float          g_wt[(size_t)NN * DD];
__device__ __nv_bfloat16  g_wtb[(size_t)NN * DD];
__device__ __nv_bfloat16  g_simsb[(size_t)BQ * NN];
__device__ int            g_cand[BQ * NCAND];

// ---------------------------------------------------------------------------
// Kernel 1: normalize queries -> fp32 + bf16
// ---------------------------------------------------------------------------
__global__ __launch_bounds__(128) void normalize_kernel(const float* __restrict__ q) {
    int row = blockIdx.x;
    const float* src = q + (size_t)row * DD;
    float v[4];
    float s = 0.f;
#pragma unroll
    for (int i = 0; i < 4; i++) { v[i] = src[threadIdx.x + i * 128]; s += v[i] * v[i]; }
#pragma unroll
    for (int o = 16; o > 0; o >>= 1) s += __shfl_xor_sync(0xffffffffu, s, o);
    __shared__ float red[4];
    if ((threadIdx.x & 31) == 0) red[threadIdx.x >> 5] = s;
    __syncthreads();
    float inv = rsqrtf(red[0] + red[1] + red[2] + red[3]);
#pragma unroll
    for (int i = 0; i < 4; i++) {
        float f = v[i] * inv;
        int d = threadIdx.x + i * 128;
        g_qn[(size_t)row * DD + d]  = f;
        g_qnb[(size_t)row * DD + d] = __float2bfloat16(f);
    }
}

// ---------------------------------------------------------------------------
// Kernel 2: transpose W[D,N] -> W_t[N,D] (fp32 + bf16)
// ---------------------------------------------------------------------------
__global__ __launch_bounds__(256) void transpose_kernel(const float* __restrict__ W) {
    __shared__ float tile[32][33];
    int bx = blockIdx.x, by = blockIdx.y;
    int tx = threadIdx.x, ty = threadIdx.y;
#pragma unroll
    for (int k = 0; k < 4; k++) {
        int d = by * 32 + ty + k * 8;
        int n = bx * 32 + tx;
        tile[ty + k * 8][tx] = W[(size_t)d * NN + n];
    }
    __syncthreads();
#pragma unroll
    for (int k = 0; k < 4; k++) {
        int n = bx * 32 + ty + k * 8;
        int d = by * 32 + tx;
        float v = tile[tx][ty + k * 8];
        g_wt [(size_t)n * DD + d] = v;
        g_wtb[(size_t)n * DD + d] = __float2bfloat16(v);
    }
}

// ---------------------------------------------------------------------------
// Kernel 3: bf16 HMMA GEMM, 3-stage cp.async pipeline.
// CTA tile 128x128, BK=64, 8 warps (2m x 4n), warp tile 64x32.
// ---------------------------------------------------------------------------
#define BKG 64
#define STG_BYTES 16384
#define AOFFS(s) ((uint32_t)((s) * STG_BYTES))
#define BOFFS(s) ((uint32_t)(49152 + (s) * STG_BYTES))
#define SMEM_TOTAL 98304   // 3xA(16K) + 3xB(16K); epilogue reuses first 32K

__global__ __launch_bounds__(256, 2) void gemm_kernel() {
    extern __shared__ char smem[];
    const uint32_t sb = smem_u32(smem);
    const int tid = threadIdx.x, wid = tid >> 5, lane = tid & 31;
    const int q0 = blockIdx.x * 128;
    const int nb = blockIdx.y * 128;

    const int ldrow = tid >> 3;
    const int ldseg = tid & 7;

    auto issue = [&](int kc, int stg) {
        const __nv_bfloat16* As = g_qnb + (size_t)q0 * DD + kc * BKG;
        const __nv_bfloat16* Bs = g_wtb + (size_t)nb * DD + kc * BKG;
#pragma unroll
        for (int i = 0; i < 4; i++) {
            int row = ldrow + i * 32;
            uint32_t off = sw128((uint32_t)(row * 128 + ldseg * 16));
            CP_ASYNC16(sb + AOFFS(stg) + off, As + (size_t)row * DD + ldseg * 8);
            CP_ASYNC16(sb + BOFFS(stg) + off, Bs + (size_t)row * DD + ldseg * 8);
        }
        CP_COMMIT();
    };

    float c[4][4][4];
#pragma unroll
    for (int mi = 0; mi < 4; mi++)
#pragma unroll
        for (int ni = 0; ni < 4; ni++)
#pragma unroll
            for (int r = 0; r < 4; r++) c[mi][ni][r] = 0.f;

    const int wm = (wid >> 2) * 64;
    const int wn = (wid & 3) * 32;
    const int lrow = lane & 15;
    const int lkh  = lane >> 4;

    issue(0, 0);
    issue(1, 1);

#pragma unroll 1
    for (int kc = 0; kc < 8; kc++) {
        const int stg = kc % 3;
        if (kc == 7) { CP_WAIT(0); } else { CP_WAIT(1); }
        __syncthreads();
        if (kc + 2 < 8) issue(kc + 2, (kc + 2) % 3);

        const uint32_t ab = sb + AOFFS(stg);
        const uint32_t bb = sb + BOFFS(stg);
#pragma unroll
        for (int ks = 0; ks < 4; ks++) {
            const int k0 = ks * 16;
            uint32_t a[4][4];
#pragma unroll
            for (int mi = 0; mi < 4; mi++) {
                uint32_t addr = ab + sw128((uint32_t)((wm + mi * 16 + lrow) * 128 + (k0 + lkh * 8) * 2));
                LDMATRIX_X4(a[mi][0], a[mi][1], a[mi][2], a[mi][3], addr);
            }
            uint32_t b[4][2];
#pragma unroll
            for (int nj = 0; nj < 2; nj++) {
                uint32_t r0, r1, r2, r3;
                uint32_t addr = bb + sw128((uint32_t)((wn + nj * 16 + lrow) * 128 + (k0 + lkh * 8) * 2));
                LDMATRIX_X4(r0, r1, r2, r3, addr);
                b[2 * nj][0] = r0; b[2 * nj + 1][0] = r1;
                b[2 * nj][1] = r2; b[2 * nj + 1][1] = r3;
            }
#pragma unroll
            for (int mi = 0; mi < 4; mi++)
#pragma unroll
                for (int ni = 0; ni < 4; ni++)
                    MMA_BF16(c[mi][ni], a[mi], b[ni]);
        }
        __syncthreads();
    }

    // ---- epilogue: stage C tile in smem (reuses stage 0/1 area), coalesced ----
    const int crow = lane >> 2;
    const int ccol2 = (lane & 3) * 2;
#pragma unroll
    for (int mi = 0; mi < 4; mi++)
#pragma unroll
        for (int ni = 0; ni < 4; ni++) {
            int m = wm + mi * 16 + crow;
            int n = wn + ni * 8 + ccol2;
            __nv_bfloat162 p0 = __float22bfloat162_rn(make_float2(c[mi][ni][0], c[mi][ni][1]));
            __nv_bfloat162 p1 = __float22bfloat162_rn(make_float2(c[mi][ni][2], c[mi][ni][3]));
            *(__nv_bfloat162*)(smem + m * 256 + n * 2)       = p0;
            *(__nv_bfloat162*)(smem + (m + 8) * 256 + n * 2) = p1;
        }
    __syncthreads();
#pragma unroll
    for (int i = 0; i < 8; i++) {
        int idx = tid + i * 256;
        int m = idx >> 4, ch = idx & 15;
        uint4 v = *(uint4*)(smem + m * 256 + ch * 16);
        *(uint4*)(g_simsb + (size_t)(q0 + m) * NN + nb + ch * 8) = v;
    }
}

// ---------------------------------------------------------------------------
// Kernel 4: per-query top-32 candidates from bf16 sims.
// Scan: hmax2 8-way prefilter -> rare insertion branch.
// Select: single-warp tournament over 256 descending-sorted head lists.
// ---------------------------------------------------------------------------
#define TL 8
__global__ __launch_bounds__(256) void cand_kernel() {
    const int q = blockIdx.x;
    const uint4* row = (const uint4*)(g_simsb + (size_t)q * NN);
    const int tid = threadIdx.x;

    float tv[TL]; int ti[TL];
#pragma unroll
    for (int i = 0; i < TL; i++) { tv[i] = -CUDART_INF_F; ti[i] = 0x7fffffff; }
    float thr = -CUDART_INF_F;

#pragma unroll 4
    for (int i = 0; i < 64; i++) {
        const int j = tid + i * 256;
        uint4 v = row[j];
        __nv_bfloat162 p0 = *(__nv_bfloat162*)&v.x;
        __nv_bfloat162 p1 = *(__nv_bfloat162*)&v.y;
        __nv_bfloat162 p2 = *(__nv_bfloat162*)&v.z;
        __nv_bfloat162 p3 = *(__nv_bfloat162*)&v.w;
        __nv_bfloat162 m = __hmax2(__hmax2(p0, p1), __hmax2(p2, p3));
        float mx = fmaxf(__low2float(m), __high2float(m));
        if (mx > thr) {   // rare path
            uint32_t w[4] = {v.x, v.y, v.z, v.w};
#pragma unroll
            for (int e = 0; e < 4; e++) {
                __nv_bfloat162 b2 = *(__nv_bfloat162*)&w[e];
#pragma unroll
                for (int h = 0; h < 2; h++) {
                    float x = h ? __high2float(b2) : __low2float(b2);
                    int   n = j * 8 + e * 2 + h;
                    if (x > tv[0]) {
                        int pos = 0;
#pragma unroll
                        for (int s = 0; s < TL - 1; s++)
                            if (pos == s && tv[s + 1] < x) {
                                tv[s] = tv[s + 1]; ti[s] = ti[s + 1]; pos = s + 1;
                            }
                        tv[pos] = x; ti[pos] = n;
                    }
                }
            }
            thr = tv[0];
        }
    }

    // dump per-thread lists DESCENDING
    __shared__ float sv[256 * TL];
    __shared__ int   si[256 * TL];
#pragma unroll
    for (int i = 0; i < TL; i++) {
        sv[tid * TL + i] = tv[TL - 1 - i];
        si[tid * TL + i] = ti[TL - 1 - i];
    }
    __syncthreads();

    // single-warp tournament: lane l owns threads l*8 .. l*8+7
    if (tid < 32) {
        const int l = tid;
        float hv[8]; int hx[8]; int hp[8];
#pragma unroll
        for (int s = 0; s < 8; s++) {
            int t = l * 8 + s;
            hv[s] = sv[t * TL]; hx[s] = si[t * TL]; hp[s] = 0;
        }
#pragma unroll 1
        for (int sel = 0; sel < NCAND; sel++) {
            // local argmax over 8 heads
            float bv = -CUDART_INF_F; int bi = 0x7fffffff; int bs = 0;
#pragma unroll
            for (int s = 0; s < 8; s++)
                if (hv[s] > bv || (hv[s] == bv && hx[s] < bi)) { bv = hv[s]; bi = hx[s]; bs = s; }
            // warp argmax
            float wv = bv; int wi = bi; int wl = l;
#pragma unroll
            for (int off = 16; off > 0; off >>= 1) {
                float ov = __shfl_xor_sync(0xffffffffu, wv, off);
                int   oi = __shfl_xor_sync(0xffffffffu, wi, off);
                int   ol = __shfl_xor_sync(0xffffffffu, wl, off);
                if (ov > wv || (ov == wv && oi < wi)) { wv = ov; wi = oi; wl = ol; }
            }
            if (l == wl) {
                g_cand[q * NCAND + sel] = wi;
                int t = l * 8 + bs;
                hp[bs]++;
                if (hp[bs] < TL) { hv[bs] = sv[t * TL + hp[bs]]; hx[bs] = si[t * TL + hp[bs]]; }
                else             { hv[bs] = -CUDART_INF_F;      hx[bs] = 0x7fffffff; }
            }
        }
    }
}

// ---------------------------------------------------------------------------
// Kernel 5: sequential-fp32 rescore of 32 candidates, top-16, write outputs
// ---------------------------------------------------------------------------
#define CHUNK 128
#define CPITCH 129

__global__ __launch_bounds__(256) void refine_kernel(const float* __restrict__ label,
                                                     float* __restrict__ out_scores,
                                                     float* __restrict__ out_idx_f,
                                                     float* __restrict__ out_seqs,
                                                     float* __restrict__ out_labels) {
    const int q = blockIdx.x;
    const int tid = threadIdx.x;

    __shared__ float qn_s[DD];
    __shared__ float chunk[NCAND * CPITCH];
    __shared__ float cv[NCAND];
    __shared__ int   ci[NCAND];
    __shared__ int   sel_idx[KK];

    if (tid < NCAND) ci[tid] = g_cand[q * NCAND + tid];
    for (int d = tid; d < DD; d += 256) qn_s[d] = g_qn[(size_t)q * DD + d];
    __syncthreads();

    float acc = 0.f;
#pragma unroll 1
    for (int ch = 0; ch < DD / CHUNK; ch++) {
        for (int idx = tid; idx < NCAND * CHUNK; idx += 256) {
            int c = idx >> 7, d = idx & (CHUNK - 1);
            chunk[c * CPITCH + d] = g_wt[(size_t)ci[c] * DD + ch * CHUNK + d];
        }
        __syncthreads();
        if (tid < NCAND) {
#pragma unroll
            for (int d = 0; d < CHUNK; d++)
                acc = fmaf(chunk[tid * CPITCH + d], qn_s[ch * CHUNK + d], acc);
        }
        __syncthreads();
    }
    if (tid < NCAND) cv[tid] = acc;
    __syncthreads();

    if (tid == 0) {
        bool used[NCAND] = {};
        for (int r = 0; r < KK; r++) {
            float best = -CUDART_INF_F; int bj = -1; int bidx = 0x7fffffff;
            for (int j = 0; j < NCAND; j++) {
                if (used[j]) continue;
                if (cv[j] > best || (cv[j] == best && ci[j] < bidx)) {
                    best = cv[j]; bj = j; bidx = ci[j];
                }
            }
            used[bj] = true;
            sel_idx[r] = ci[bj];
            out_scores[q * KK + r] = best;
            out_idx_f [q * KK + r] = (float)ci[bj];
            out_labels[q * KK + r] = label[ci[bj]];
        }
    }
    __syncthreads();

#pragma unroll 1
    for (int r = 0; r < KK; r++) {
        const float* row = g_wt + (size_t)sel_idx[r] * DD;
        float* dst = out_seqs + ((size_t)q * KK + r) * DD;
        for (int d = tid; d < DD; d += 256) dst[d] = row[d];
    }
}

// ---------------------------------------------------------------------------
// Launcher
// ---------------------------------------------------------------------------
extern "C" void kernel_launch(void* const* d_in, const int* in_sizes, int n_in,
                              void* d_out, int out_size) {
    const float* queries = (const float*)d_in[0];
    const float* weight  = (const float*)d_in[1];
    const float* label   = (const float*)d_in[2];

    float* out = (float*)d_out;
    float* out_scores = out;
    float* out_idx_f  = out + BQ * KK;
    float* out_seqs   = out + 2 * BQ * KK;
    float* out_labels = out + 2 * BQ * KK + (size_t)BQ * KK * DD;

    cudaFuncSetAttribute(gemm_kernel, cudaFuncAttributeMaxDynamicSharedMemorySize, SMEM_TOTAL);

    normalize_kernel<<<BQ, 128>>>(queries);
    transpose_kernel<<<dim3(NN / 32, DD / 32), dim3(32, 8)>>>(weight);
    gemm_kernel<<<dim3(BQ / 128, NN / 128), 256, SMEM_TOTAL>>>();
    cand_kernel<<<BQ, 256>>>();
    refine_kernel<<<BQ, 256>>>(label, out_scores, out_idx_f, out_seqs, out_labels);
}

// round 6
// speedup vs baseline: 11.9087x; 1.9560x over previous
#include <cuda_runtime.h>
#include <cuda_bf16.h>
#include <math_constants.h>
#include <cstdint>

// Problem constants
#define BQ 1024
#define DD 512
#define NN 131072
#define KK 16
#define NCAND 32
#define NTILES (NN / 128)       // 1024 n-tiles
#define PPT 8                   // partial entries per (query, tile)

// ---------------------------------------------------------------------------
// Helpers
// ---------------------------------------------------------------------------
__device__ __forceinline__ uint32_t smem_u32(const void* p) {
    uint32_t a;
    asm("{ .reg .u64 t; cvta.to.shared.u64 t, %1; cvt.u32.u64 %0, t; }" : "=r"(a) : "l"(p));
    return a;
}
__device__ __forceinline__ uint32_t sw128(uint32_t o) { return o ^ ((o >> 3) & 0x70); }

#define CP_ASYNC16(smem_addr, gptr) \
    asm volatile("cp.async.cg.shared.global [%0], [%1], 16;" :: "r"(smem_addr), "l"(gptr))
#define CP_COMMIT() asm volatile("cp.async.commit_group;")
#define CP_WAIT(N)  asm volatile("cp.async.wait_group %0;" :: "n"(N))

#define LDMATRIX_X4(r0, r1, r2, r3, addr) \
    asm volatile("ldmatrix.sync.aligned.m8n8.x4.shared.b16 {%0,%1,%2,%3}, [%4];" \
        : "=r"(r0), "=r"(r1), "=r"(r2), "=r"(r3) : "r"(addr))

#define MMA_BF16(c, a, b) \
    asm volatile("mma.sync.aligned.m16n8k16.row.col.f32.bf16.bf16.f32 " \
        "{%0,%1,%2,%3}, {%4,%5,%6,%7}, {%8,%9}, {%0,%1,%2,%3};" \
        : "+f"((c)[0]), "+f"((c)[1]), "+f"((c)[2]), "+f"((c)[3]) \
        : "r"((a)[0]), "r"((a)[1]), "r"((a)[2]), "r"((a)[3]), "r"((b)[0]), "r"((b)[1]))

// ---------------------------------------------------------------------------
// Scratch
// ---------------------------------------------------------------------------
__device__ float          g_qn[BQ * DD];
__device__ __nv_bfloat16  g_qnb[BQ * DD];
__device__ float          g_wt[(size_t)NN * DD];
__device__ __nv_bfloat16  g_wtb[(size_t)NN * DD];
__device__ float          g_pv[(size_t)BQ * NTILES * PPT];   // partial top values 32MB
__device__ int            g_pi[(size_t)BQ * NTILES * PPT];   // partial top indices 32MB
__device__ int            g_cand[BQ * NCAND];

// ---------------------------------------------------------------------------
// Kernel 1: normalize queries -> fp32 + bf16
// ---------------------------------------------------------------------------
__global__ __launch_bounds__(128) void normalize_kernel(const float* __restrict__ q) {
    int row = blockIdx.x;
    const float* src = q + (size_t)row * DD;
    float v[4];
    float s = 0.f;
#pragma unroll
    for (int i = 0; i < 4; i++) { v[i] = src[threadIdx.x + i * 128]; s += v[i] * v[i]; }
#pragma unroll
    for (int o = 16; o > 0; o >>= 1) s += __shfl_xor_sync(0xffffffffu, s, o);
    __shared__ float red[4];
    if ((threadIdx.x & 31) == 0) red[threadIdx.x >> 5] = s;
    __syncthreads();
    float inv = rsqrtf(red[0] + red[1] + red[2] + red[3]);
#pragma unroll
    for (int i = 0; i < 4; i++) {
        float f = v[i] * inv;
        int d = threadIdx.x + i * 128;
        g_qn[(size_t)row * DD + d]  = f;
        g_qnb[(size_t)row * DD + d] = __float2bfloat16(f);
    }
}

// ---------------------------------------------------------------------------
// Kernel 2: transpose W[D,N] -> W_t[N,D] (fp32 + bf16)
// ---------------------------------------------------------------------------
__global__ __launch_bounds__(256) void transpose_kernel(const float* __restrict__ W) {
    __shared__ float tile[32][33];
    int bx = blockIdx.x, by = blockIdx.y;
    int tx = threadIdx.x, ty = threadIdx.y;
#pragma unroll
    for (int k = 0; k < 4; k++) {
        int d = by * 32 + ty + k * 8;
        int n = bx * 32 + tx;
        tile[ty + k * 8][tx] = W[(size_t)d * NN + n];
    }
    __syncthreads();
#pragma unroll
    for (int k = 0; k < 4; k++) {
        int n = bx * 32 + ty + k * 8;
        int d = by * 32 + tx;
        float v = tile[tx][ty + k * 8];
        g_wt [(size_t)n * DD + d] = v;
        g_wtb[(size_t)n * DD + d] = __float2bfloat16(v);
    }
}

// ---------------------------------------------------------------------------
// Kernel 3: bf16 HMMA GEMM + fused per-(row, half-tile) top-4 selection.
// CTA tile 128x128, BK=64, 8 warps (2m x 4n), 3-stage cp.async pipeline.
// No sims written to gmem: only 8 (val,idx) partials per (query,tile).
// ---------------------------------------------------------------------------
#define BKG 64
#define STG_BYTES 16384
#define AOFFS(s) ((uint32_t)((s) * STG_BYTES))
#define BOFFS(s) ((uint32_t)(49152 + (s) * STG_BYTES))
#define SMEM_TOTAL 98304

__global__ __launch_bounds__(256, 2) void gemm_kernel() {
    extern __shared__ char smem[];
    const uint32_t sb = smem_u32(smem);
    const int tid = threadIdx.x, wid = tid >> 5, lane = tid & 31;
    const int q0 = blockIdx.x * 128;
    const int nb = blockIdx.y * 128;

    const int ldrow = tid >> 3;
    const int ldseg = tid & 7;

    auto issue = [&](int kc, int stg) {
        const __nv_bfloat16* As = g_qnb + (size_t)q0 * DD + kc * BKG;
        const __nv_bfloat16* Bs = g_wtb + (size_t)nb * DD + kc * BKG;
#pragma unroll
        for (int i = 0; i < 4; i++) {
            int row = ldrow + i * 32;
            uint32_t off = sw128((uint32_t)(row * 128 + ldseg * 16));
            CP_ASYNC16(sb + AOFFS(stg) + off, As + (size_t)row * DD + ldseg * 8);
            CP_ASYNC16(sb + BOFFS(stg) + off, Bs + (size_t)row * DD + ldseg * 8);
        }
        CP_COMMIT();
    };

    float c[4][4][4];
#pragma unroll
    for (int mi = 0; mi < 4; mi++)
#pragma unroll
        for (int ni = 0; ni < 4; ni++)
#pragma unroll
            for (int r = 0; r < 4; r++) c[mi][ni][r] = 0.f;

    const int wm = (wid >> 2) * 64;
    const int wn = (wid & 3) * 32;
    const int lrow = lane & 15;
    const int lkh  = lane >> 4;

    issue(0, 0);
    issue(1, 1);

#pragma unroll 1
    for (int kc = 0; kc < 8; kc++) {
        const int stg = kc % 3;
        if (kc == 7) { CP_WAIT(0); } else { CP_WAIT(1); }
        __syncthreads();
        if (kc + 2 < 8) issue(kc + 2, (kc + 2) % 3);

        const uint32_t ab = sb + AOFFS(stg);
        const uint32_t bb = sb + BOFFS(stg);
#pragma unroll
        for (int ks = 0; ks < 4; ks++) {
            const int k0 = ks * 16;
            uint32_t a[4][4];
#pragma unroll
            for (int mi = 0; mi < 4; mi++) {
                uint32_t addr = ab + sw128((uint32_t)((wm + mi * 16 + lrow) * 128 + (k0 + lkh * 8) * 2));
                LDMATRIX_X4(a[mi][0], a[mi][1], a[mi][2], a[mi][3], addr);
            }
            uint32_t b[4][2];
#pragma unroll
            for (int nj = 0; nj < 2; nj++) {
                uint32_t r0, r1, r2, r3;
                uint32_t addr = bb + sw128((uint32_t)((wn + nj * 16 + lrow) * 128 + (k0 + lkh * 8) * 2));
                LDMATRIX_X4(r0, r1, r2, r3, addr);
                b[2 * nj][0] = r0; b[2 * nj + 1][0] = r1;
                b[2 * nj][1] = r2; b[2 * nj + 1][1] = r3;
            }
#pragma unroll
            for (int mi = 0; mi < 4; mi++)
#pragma unroll
                for (int ni = 0; ni < 4; ni++)
                    MMA_BF16(c[mi][ni], a[mi], b[ni]);
        }
        __syncthreads();
    }

    // ---- stage C tile (128x128 bf16) in smem ----
    const int crow = lane >> 2;
    const int ccol2 = (lane & 3) * 2;
#pragma unroll
    for (int mi = 0; mi < 4; mi++)
#pragma unroll
        for (int ni = 0; ni < 4; ni++) {
            int m = wm + mi * 16 + crow;
            int n = wn + ni * 8 + ccol2;
            __nv_bfloat162 p0 = __float22bfloat162_rn(make_float2(c[mi][ni][0], c[mi][ni][1]));
            __nv_bfloat162 p1 = __float22bfloat162_rn(make_float2(c[mi][ni][2], c[mi][ni][3]));
            *(__nv_bfloat162*)(smem + m * 256 + n * 2)       = p0;
            *(__nv_bfloat162*)(smem + (m + 8) * 256 + n * 2) = p1;
        }
    __syncthreads();

    // ---- fused selection: 2 threads per query row, each owns 64 cols ----
    {
        const int row  = tid >> 1;     // 0..127
        const int half = tid & 1;      // 0..1
        float v0 = -CUDART_INF_F, v1 = -CUDART_INF_F, v2 = -CUDART_INF_F, v3 = -CUDART_INF_F;
        int   i0 = 0x7fffffff, i1 = 0x7fffffff, i2 = 0x7fffffff, i3 = 0x7fffffff;
        const int rot = 2 * (row & 15) + half;   // conflict-free bank rotation
#pragma unroll
        for (int p = 0; p < 32; p++) {
            int pp = (p + rot) & 31;
            uint32_t w = *(uint32_t*)(smem + row * 256 + half * 128 + pp * 4);
            __nv_bfloat162 b2 = *(__nv_bfloat162*)&w;
            float x0 = __low2float(b2);
            float x1 = __high2float(b2);
            int   n0 = nb + half * 64 + pp * 2;
#pragma unroll
            for (int h = 0; h < 2; h++) {
                float x = h ? x1 : x0;
                int   n = n0 + h;
                bool p0c = x > v0, p1c = x > v1, p2c = x > v2, p3c = x > v3;
                v3 = p2c ? v2 : (p3c ? x : v3);  i3 = p2c ? i2 : (p3c ? n : i3);
                v2 = p1c ? v1 : (p2c ? x : v2);  i2 = p1c ? i1 : (p2c ? n : i2);
                v1 = p0c ? v0 : (p1c ? x : v1);  i1 = p0c ? i0 : (p1c ? n : i1);
                v0 = p0c ? x  : v0;              i0 = p0c ? n : i0;
            }
        }
        size_t base = ((size_t)(q0 + row) * NTILES + blockIdx.y) * PPT + half * 4;
        *(float4*)(g_pv + base) = make_float4(v0, v1, v2, v3);
        *(int4*)  (g_pi + base) = make_int4(i0, i1, i2, i3);
    }
}

// ---------------------------------------------------------------------------
// Kernel 4: per-query top-32 from the 8192 partials (branchless top-8 +
// single-warp tournament).
// ---------------------------------------------------------------------------
#define TL 8
__global__ __launch_bounds__(256) void cand_kernel() {
    const int q = blockIdx.x;
    const int tid = threadIdx.x;
    const float* pv = g_pv + (size_t)q * NTILES * PPT;
    const int*   pi = g_pi + (size_t)q * NTILES * PPT;

    float tv[TL]; int ti[TL];   // descending: tv[0] max
#pragma unroll
    for (int i = 0; i < TL; i++) { tv[i] = -CUDART_INF_F; ti[i] = 0x7fffffff; }

#pragma unroll
    for (int b = 0; b < 8; b++) {
        float4 v = *(const float4*)(pv + tid * 32 + b * 4);
        int4   x = *(const int4*)(pi + tid * 32 + b * 4);
        float xs[4] = {v.x, v.y, v.z, v.w};
        int   ns[4] = {x.x, x.y, x.z, x.w};
#pragma unroll
        for (int e = 0; e < 4; e++) {
            float xx = xs[e]; int nn = ns[e];
            bool c0 = xx > tv[0], c1 = xx > tv[1], c2 = xx > tv[2], c3 = xx > tv[3];
            bool c4 = xx > tv[4], c5 = xx > tv[5], c6 = xx > tv[6], c7 = xx > tv[7];
            tv[7] = c6 ? tv[6] : (c7 ? xx : tv[7]);  ti[7] = c6 ? ti[6] : (c7 ? nn : ti[7]);
            tv[6] = c5 ? tv[5] : (c6 ? xx : tv[6]);  ti[6] = c5 ? ti[5] : (c6 ? nn : ti[6]);
            tv[5] = c4 ? tv[4] : (c5 ? xx : tv[5]);  ti[5] = c4 ? ti[4] : (c5 ? nn : ti[5]);
            tv[4] = c3 ? tv[3] : (c4 ? xx : tv[4]);  ti[4] = c3 ? ti[3] : (c4 ? nn : ti[4]);
            tv[3] = c2 ? tv[2] : (c3 ? xx : tv[3]);  ti[3] = c2 ? ti[2] : (c3 ? nn : ti[3]);
            tv[2] = c1 ? tv[1] : (c2 ? xx : tv[2]);  ti[2] = c1 ? ti[1] : (c2 ? nn : ti[2]);
            tv[1] = c0 ? tv[0] : (c1 ? xx : tv[1]);  ti[1] = c0 ? ti[0] : (c1 ? nn : ti[1]);
            tv[0] = c0 ? xx : tv[0];                 ti[0] = c0 ? nn : ti[0];
        }
    }

    __shared__ float sv[256 * TL];
    __shared__ int   si[256 * TL];
#pragma unroll
    for (int i = 0; i < TL; i++) {       // already descending
        sv[tid * TL + i] = tv[i];
        si[tid * TL + i] = ti[i];
    }
    __syncthreads();

    if (tid < 32) {
        const int l = tid;
        float hv[8]; int hx[8]; int hp[8];
#pragma unroll
        for (int s = 0; s < 8; s++) {
            int t = l * 8 + s;
            hv[s] = sv[t * TL]; hx[s] = si[t * TL]; hp[s] = 0;
        }
#pragma unroll 1
        for (int sel = 0; sel < NCAND; sel++) {
            float bv = -CUDART_INF_F; int bi = 0x7fffffff; int bs = 0;
#pragma unroll
            for (int s = 0; s < 8; s++)
                if (hv[s] > bv || (hv[s] == bv && hx[s] < bi)) { bv = hv[s]; bi = hx[s]; bs = s; }
            float wv = bv; int wi = bi; int wl = l;
#pragma unroll
            for (int off = 16; off > 0; off >>= 1) {
                float ov = __shfl_xor_sync(0xffffffffu, wv, off);
                int   oi = __shfl_xor_sync(0xffffffffu, wi, off);
                int   ol = __shfl_xor_sync(0xffffffffu, wl, off);
                if (ov > wv || (ov == wv && oi < wi)) { wv = ov; wi = oi; wl = ol; }
            }
            if (l == wl) {
                g_cand[q * NCAND + sel] = wi;
                int t = l * 8 + bs;
                hp[bs]++;
                if (hp[bs] < TL) { hv[bs] = sv[t * TL + hp[bs]]; hx[bs] = si[t * TL + hp[bs]]; }
                else             { hv[bs] = -CUDART_INF_F;      hx[bs] = 0x7fffffff; }
            }
        }
    }
}

// ---------------------------------------------------------------------------
// Kernel 5: sequential-fp32 rescore of 32 candidates, top-16, write outputs
// ---------------------------------------------------------------------------
#define CHUNK 128
#define CPITCH 129

__global__ __launch_bounds__(256) void refine_kernel(const float* __restrict__ label,
                                                     float* __restrict__ out_scores,
                                                     float* __restrict__ out_idx_f,
                                                     float* __restrict__ out_seqs,
                                                     float* __restrict__ out_labels) {
    const int q = blockIdx.x;
    const int tid = threadIdx.x;

    __shared__ float qn_s[DD];
    __shared__ float chunk[NCAND * CPITCH];
    __shared__ float cv[NCAND];
    __shared__ int   ci[NCAND];
    __shared__ int   sel_idx[KK];

    if (tid < NCAND) ci[tid] = g_cand[q * NCAND + tid];
    for (int d = tid; d < DD; d += 256) qn_s[d] = g_qn[(size_t)q * DD + d];
    __syncthreads();

    float acc = 0.f;
#pragma unroll 1
    for (int ch = 0; ch < DD / CHUNK; ch++) {
        for (int idx = tid; idx < NCAND * CHUNK; idx += 256) {
            int c = idx >> 7, d = idx & (CHUNK - 1);
            chunk[c * CPITCH + d] = g_wt[(size_t)ci[c] * DD + ch * CHUNK + d];
        }
        __syncthreads();
        if (tid < NCAND) {
#pragma unroll
            for (int d = 0; d < CHUNK; d++)
                acc = fmaf(chunk[tid * CPITCH + d], qn_s[ch * CHUNK + d], acc);
        }
        __syncthreads();
    }
    if (tid < NCAND) cv[tid] = acc;
    __syncthreads();

    if (tid == 0) {
        bool used[NCAND] = {};
        for (int r = 0; r < KK; r++) {
            float best = -CUDART_INF_F; int bj = -1; int bidx = 0x7fffffff;
            for (int j = 0; j < NCAND; j++) {
                if (used[j]) continue;
                if (cv[j] > best || (cv[j] == best && ci[j] < bidx)) {
                    best = cv[j]; bj = j; bidx = ci[j];
                }
            }
            used[bj] = true;
            sel_idx[r] = ci[bj];
            out_scores[q * KK + r] = best;
            out_idx_f [q * KK + r] = (float)ci[bj];
            out_labels[q * KK + r] = label[ci[bj]];
        }
    }
    __syncthreads();

#pragma unroll 1
    for (int r = 0; r < KK; r++) {
        const float* row = g_wt + (size_t)sel_idx[r] * DD;
        float* dst = out_seqs + ((size_t)q * KK + r) * DD;
        for (int d = tid; d < DD; d += 256) dst[d] = row[d];
    }
}

// ---------------------------------------------------------------------------
// Launcher
// ---------------------------------------------------------------------------
extern "C" void kernel_launch(void* const* d_in, const int* in_sizes, int n_in,
                              void* d_out, int out_size) {
    const float* queries = (const float*)d_in[0];
    const float* weight  = (const float*)d_in[1];
    const float* label   = (const float*)d_in[2];

    float* out = (float*)d_out;
    float* out_scores = out;
    float* out_idx_f  = out + BQ * KK;
    float* out_seqs   = out + 2 * BQ * KK;
    float* out_labels = out + 2 * BQ * KK + (size_t)BQ * KK * DD;

    cudaFuncSetAttribute(gemm_kernel, cudaFuncAttributeMaxDynamicSharedMemorySize, SMEM_TOTAL);

    normalize_kernel<<<BQ, 128>>>(queries);
    transpose_kernel<<<dim3(NN / 32, DD / 32), dim3(32, 8)>>>(weight);
    gemm_kernel<<<dim3(BQ / 128, NN / 128), 256, SMEM_TOTAL>>>();
    cand_kernel<<<BQ, 256>>>();
    refine_kernel<<<BQ, 256>>>(label, out_scores, out_idx_f, out_seqs, out_labels);
}